// round 17
// baseline (speedup 1.0000x reference)
#include <cuda_runtime.h>
#include <cuda_fp16.h>
#include <math.h>
#include <stdint.h>

#define TOKS    16384
#define NEXP    256
#define KDIM    7168
#define BM      128
#define BN      64
#define BK      64
#define NCH     (KDIM / BK)     // 112
#define THREADS 256

__device__ __align__(16) float  g_logits[(size_t)TOKS * NEXP];
__device__ __align__(16) __half g_Wlimb[2][(size_t)NEXP * KDIM];
__device__ __align__(16) __half g_Alimb[2][(size_t)TOKS * KDIM];

// ---- smem (bytes), fp16, 144B row stride, 3 stages -------------------------
#define SA_STG  36864
#define SA_L    18432
#define SB_BASE 110592
#define SB_STG  18432
#define SB_L    9216
#define SMEM_BYTES 165888

__device__ __forceinline__ uint32_t smem_u32(const void* p) {
    uint32_t a;
    asm("{ .reg .u64 t; cvta.to.shared.u64 t, %1; cvt.u32.u64 %0, t; }" : "=r"(a) : "l"(p));
    return a;
}
__device__ __forceinline__ void cp_async16(uint32_t sdst, const void* gsrc) {
    asm volatile("cp.async.cg.shared.global [%0], [%1], 16;" :: "r"(sdst), "l"(gsrc));
}
#define CP_COMMIT() asm volatile("cp.async.commit_group;" ::: "memory")
#define CP_WAIT0()  asm volatile("cp.async.wait_group 0;" ::: "memory")
#define CP_WAIT1()  asm volatile("cp.async.wait_group 1;" ::: "memory")

#define LDM4(r0, r1, r2, r3, addr) \
    asm volatile("ldmatrix.sync.aligned.m8n8.x4.shared.b16 {%0,%1,%2,%3}, [%4];" \
        : "=r"(r0), "=r"(r1), "=r"(r2), "=r"(r3) : "r"(addr))

__device__ __forceinline__ void mma16816(float d[4],
                                         uint32_t a0, uint32_t a1, uint32_t a2, uint32_t a3,
                                         uint32_t b0, uint32_t b1) {
    asm volatile(
        "mma.sync.aligned.m16n8k16.row.col.f32.f16.f16.f32 "
        "{%0,%1,%2,%3}, {%4,%5,%6,%7}, {%8,%9}, {%0,%1,%2,%3};"
        : "+f"(d[0]), "+f"(d[1]), "+f"(d[2]), "+f"(d[3])
        : "r"(a0), "r"(a1), "r"(a2), "r"(a3), "r"(b0), "r"(b1));
}

// split fp32 pair (scaled x64) into 2 packed fp16x2 limbs
__device__ __forceinline__ void split_pair(float v0, float v1,
                                           uint32_t& h, uint32_t& m) {
    v0 *= 64.0f; v1 *= 64.0f;
    __half2 h2 = __floats2half2_rn(v0, v1);
    h = *reinterpret_cast<uint32_t*>(&h2);
    float2 hf = __half22float2(h2);
    __half2 m2 = __floats2half2_rn(v0 - hf.x, v1 - hf.y);
    m = *reinterpret_cast<uint32_t*>(&m2);
}

// ---------------------------------------------------------------------------
__global__ void gate_wconv_kernel(const float* __restrict__ W) {
    int i = blockIdx.x * blockDim.x + threadIdx.x;
    if (i >= NEXP * KDIM) return;
    float v = W[i] * 64.0f;
    __half h = __float2half_rn(v);
    float r = v - __half2float(h);
    g_Wlimb[0][i] = h;
    g_Wlimb[1][i] = __float2half_rn(r);
}

// A limb pre-conversion: 16 elems/thread, batched loads (MLP=4), uint4 stores
__global__ void gate_aconv_kernel(const float* __restrict__ X) {
    size_t base = ((size_t)blockIdx.x * blockDim.x + threadIdx.x) * 16;
    if (base >= (size_t)TOKS * KDIM) return;

    float4 v[4];
    #pragma unroll
    for (int q = 0; q < 4; q++)
        v[q] = *(const float4*)(X + base + q * 4);

    uint32_t h[8], m[8];
    #pragma unroll
    for (int q = 0; q < 4; q++) {
        split_pair(v[q].x, v[q].y, h[2 * q],     m[2 * q]);
        split_pair(v[q].z, v[q].w, h[2 * q + 1], m[2 * q + 1]);
    }

    uint4* dh = (uint4*)((char*)g_Alimb[0] + base * 2);
    uint4* dm = (uint4*)((char*)g_Alimb[1] + base * 2);
    dh[0] = make_uint4(h[0], h[1], h[2], h[3]);
    dh[1] = make_uint4(h[4], h[5], h[6], h[7]);
    dm[0] = make_uint4(m[0], m[1], m[2], m[3]);
    dm[1] = make_uint4(m[4], m[5], m[6], m[7]);
}

// ---------------------------------------------------------------------------
// mma.sync fp16 2-limb / 3-product GEMM, cp.async 3-stage + ldmatrix
// (byte-identical to the validated round-15 kernel)
// ---------------------------------------------------------------------------
__global__ __launch_bounds__(THREADS)
void gate_mma_gemm() {
    extern __shared__ char smem[];
    const uint32_t sbu = smem_u32(smem);

    const int tid  = threadIdx.x;
    const int lane = tid & 31;
    const int wid  = tid >> 5;
    const int wm   = wid & 3;
    const int wn   = wid >> 2;
    const int g    = lane >> 2;
    const int t    = lane & 3;

    const int bn = blockIdx.x;
    const int bm = blockIdx.y;
    const int t0 = bm * BM;
    const int n0 = bn * BN;

    const int j = lane >> 3, r = lane & 7;
    const uint32_t aL = (uint32_t)((wm * 32 + (j & 1) * 8 + r) * 144 + (j >> 1) * 16);
    const uint32_t bL = (uint32_t)((wn * 32 + (j >> 1) * 8 + r) * 144 + (j & 1) * 16);

    float acc_hh[2][4][4], acc_cr[2][4][4], tot[2][4][4];
    #pragma unroll
    for (int i = 0; i < 2; i++)
        #pragma unroll
        for (int jj = 0; jj < 4; jj++)
            #pragma unroll
            for (int q = 0; q < 4; q++) {
                acc_hh[i][jj][q] = 0.0f; acc_cr[i][jj][q] = 0.0f; tot[i][jj][q] = 0.0f;
            }

    auto issue_ab = [&](int kt, int st) {
        #pragma unroll
        for (int L = 0; L < 2; L++) {
            const __half* gA = g_Alimb[L] + (size_t)t0 * KDIM + kt * BK;
            uint32_t sA = sbu + (uint32_t)st * SA_STG + (uint32_t)L * SA_L;
            #pragma unroll
            for (int q = 0; q < 4; q++) {
                int line = q * 256 + tid;
                int row  = line >> 3, c = line & 7;
                cp_async16(sA + (uint32_t)row * 144 + (uint32_t)c * 16,
                           gA + (size_t)row * KDIM + c * 8);
            }
            const __half* gB = g_Wlimb[L] + (size_t)n0 * KDIM + kt * BK;
            uint32_t sB = sbu + SB_BASE + (uint32_t)st * SB_STG + (uint32_t)L * SB_L;
            #pragma unroll
            for (int q = 0; q < 2; q++) {
                int line = q * 256 + tid;
                int row  = line >> 3, c = line & 7;
                cp_async16(sB + (uint32_t)row * 144 + (uint32_t)c * 16,
                           gB + (size_t)row * KDIM + c * 8);
            }
        }
    };

    issue_ab(0, 0); CP_COMMIT();
    issue_ab(1, 1); CP_COMMIT();
    CP_WAIT1();
    __syncthreads();

    int cs = 0, ps = 2;
    for (int kt = 0; kt < NCH; kt++) {
        const bool more = (kt + 2 < NCH);
        if (more) { issue_ab(kt + 2, ps); CP_COMMIT(); }

        const uint32_t A0 = sbu + (uint32_t)cs * SA_STG + aL;
        const uint32_t A1 = A0 + SA_L;
        const uint32_t B0 = sbu + SB_BASE + (uint32_t)cs * SB_STG + bL;
        const uint32_t B1 = B0 + SB_L;

        #pragma unroll
        for (int ks = 0; ks < 4; ks++) {
            const uint32_t ko = (uint32_t)ks * 32;
            uint32_t Ah[2][4], Am[2][4], Bh[8], Bm[8];
            LDM4(Ah[0][0], Ah[0][1], Ah[0][2], Ah[0][3], A0 + ko);
            LDM4(Ah[1][0], Ah[1][1], Ah[1][2], Ah[1][3], A0 + 2304 + ko);
            LDM4(Am[0][0], Am[0][1], Am[0][2], Am[0][3], A1 + ko);
            LDM4(Am[1][0], Am[1][1], Am[1][2], Am[1][3], A1 + 2304 + ko);
            LDM4(Bh[0], Bh[1], Bh[2], Bh[3], B0 + ko);
            LDM4(Bh[4], Bh[5], Bh[6], Bh[7], B0 + 2304 + ko);
            LDM4(Bm[0], Bm[1], Bm[2], Bm[3], B1 + ko);
            LDM4(Bm[4], Bm[5], Bm[6], Bm[7], B1 + 2304 + ko);

            #pragma unroll
            for (int m2 = 0; m2 < 2; m2++)
                #pragma unroll
                for (int n4 = 0; n4 < 4; n4++)
                    mma16816(acc_hh[m2][n4], Ah[m2][0], Ah[m2][1], Ah[m2][2], Ah[m2][3],
                             Bh[2 * n4], Bh[2 * n4 + 1]);
            #pragma unroll
            for (int m2 = 0; m2 < 2; m2++)
                #pragma unroll
                for (int n4 = 0; n4 < 4; n4++)
                    mma16816(acc_cr[m2][n4], Ah[m2][0], Ah[m2][1], Ah[m2][2], Ah[m2][3],
                             Bm[2 * n4], Bm[2 * n4 + 1]);
            #pragma unroll
            for (int m2 = 0; m2 < 2; m2++)
                #pragma unroll
                for (int n4 = 0; n4 < 4; n4++)
                    mma16816(acc_cr[m2][n4], Am[m2][0], Am[m2][1], Am[m2][2], Am[m2][3],
                             Bh[2 * n4], Bh[2 * n4 + 1]);
        }

        if (more) CP_WAIT1(); else CP_WAIT0();
        __syncthreads();

        if ((kt & 31) == 31) {
            #pragma unroll
            for (int m2 = 0; m2 < 2; m2++)
                #pragma unroll
                for (int n4 = 0; n4 < 4; n4++)
                    #pragma unroll
                    for (int q = 0; q < 4; q++) {
                        tot[m2][n4][q] += acc_hh[m2][n4][q];
                        acc_hh[m2][n4][q] = 0.0f;
                    }
        }
        cs = (cs == 2) ? 0 : cs + 1;
        ps = (ps == 2) ? 0 : ps + 1;
    }

    const float INV = 1.0f / 4096.0f;
    #pragma unroll
    for (int m2 = 0; m2 < 2; m2++) {
        #pragma unroll
        for (int n4 = 0; n4 < 4; n4++) {
            float f0 = ((tot[m2][n4][0] + acc_hh[m2][n4][0]) + acc_cr[m2][n4][0]) * INV;
            float f1 = ((tot[m2][n4][1] + acc_hh[m2][n4][1]) + acc_cr[m2][n4][1]) * INV;
            float f2 = ((tot[m2][n4][2] + acc_hh[m2][n4][2]) + acc_cr[m2][n4][2]) * INV;
            float f3 = ((tot[m2][n4][3] + acc_hh[m2][n4][3]) + acc_cr[m2][n4][3]) * INV;
            const int row = t0 + wm * 32 + m2 * 16 + g;
            const int col = n0 + wn * 32 + n4 * 8 + 2 * t;
            *(float2*)(g_logits + (size_t)row * NEXP + col)       = make_float2(f0, f1);
            *(float2*)(g_logits + (size_t)(row + 8) * NEXP + col) = make_float2(f2, f3);
        }
    }
}

// ---------------------------------------------------------------------------
// Routing: one warp per token (validated rounds 2-15)
// ---------------------------------------------------------------------------
__global__ void gate_route_kernel(const float* __restrict__ bias,
                                  float* __restrict__ out_w,
                                  float* __restrict__ out_i,
                                  int Tn) {
    const int warp = (blockIdx.x * blockDim.x + threadIdx.x) >> 5;
    if (warp >= Tn) return;
    const int lane = threadIdx.x & 31;
    const unsigned FULL = 0xffffffffu;

    const float* row = g_logits + (size_t)warp * NEXP;
    float4 v0 = *(const float4*)(row + lane * 8);
    float4 v1 = *(const float4*)(row + lane * 8 + 4);
    float zz[8] = {v0.x, v0.y, v0.z, v0.w, v1.x, v1.y, v1.z, v1.w};

    float sc[8], sb8[8];
    #pragma unroll
    for (int jj = 0; jj < 8; jj++) {
        float s = 1.0f / (1.0f + expf(-zz[jj]));
        sc[jj]  = s;
        sb8[jj] = s + bias[lane * 8 + jj];
    }

    float m1 = -INFINITY, m2 = -INFINITY;
    #pragma unroll
    for (int jj = 0; jj < 8; jj++) {
        float v = sb8[jj];
        if (v > m1) { m2 = m1; m1 = v; }
        else if (v > m2) { m2 = v; }
    }
    #pragma unroll
    for (int off = 1; off <= 2; off <<= 1) {
        float o1 = __shfl_xor_sync(FULL, m1, off);
        float o2 = __shfl_xor_sync(FULL, m2, off);
        if (o1 > m1) { m2 = fmaxf(m1, o2); m1 = o1; }
        else         { m2 = fmaxf(m2, o1); }
    }
    float gsum = m1 + m2;

    float gs[8];
    #pragma unroll
    for (int gI = 0; gI < 8; gI++) gs[gI] = __shfl_sync(FULL, gsum, gI * 4);

    int chosen = 0;
    #pragma unroll
    for (int it = 0; it < 4; it++) {
        float best = -INFINITY; int bg = 0;
        #pragma unroll
        for (int gI = 0; gI < 8; gI++) {
            if (!((chosen >> gI) & 1) && gs[gI] > best) { best = gs[gI]; bg = gI; }
        }
        chosen |= 1 << bg;
    }
    const bool kept = (chosen >> (lane >> 2)) & 1;

    float v[8];
    #pragma unroll
    for (int jj = 0; jj < 8; jj++) v[jj] = kept ? sb8[jj] : -INFINITY;

    float my_w = 0.0f; int my_i = 0;
    float wsum = 0.0f;

    #pragma unroll
    for (int it = 0; it < 8; it++) {
        float bv = -INFINITY; int bi = 0x7fffffff; float bsco = 0.0f;
        #pragma unroll
        for (int jj = 0; jj < 8; jj++) {
            if (v[jj] > bv) { bv = v[jj]; bi = lane * 8 + jj; bsco = sc[jj]; }
        }
        #pragma unroll
        for (int off = 16; off; off >>= 1) {
            float ov = __shfl_xor_sync(FULL, bv, off);
            int   oi = __shfl_xor_sync(FULL, bi, off);
            float os = __shfl_xor_sync(FULL, bsco, off);
            if (ov > bv || (ov == bv && oi < bi)) { bv = ov; bi = oi; bsco = os; }
        }
        if (lane == it) { my_w = bsco; my_i = bi; }
        if ((bi >> 3) == lane) v[bi & 7] = -INFINITY;
        wsum += bsco;
    }

    if (lane < 8) {
        out_w[(size_t)warp * 8 + lane] = (my_w / wsum) * 2.5f;
        out_i[(size_t)warp * 8 + lane] = (float)my_i;
    }
}

// ---------------------------------------------------------------------------
extern "C" void kernel_launch(void* const* d_in, const int* in_sizes, int n_in,
                              void* d_out, int out_size) {
    const float* x    = (const float*)d_in[0];   // [T, 7168]
    const float* w    = (const float*)d_in[1];   // [256, 7168]
    const float* bias = (const float*)d_in[2];   // [256]

    const int Tn = in_sizes[0] / KDIM;

    cudaFuncSetAttribute(gate_mma_gemm,
                         cudaFuncAttributeMaxDynamicSharedMemorySize, SMEM_BYTES);

    gate_wconv_kernel<<<(NEXP * KDIM + 255) / 256, 256>>>(w);

    const size_t atot = (size_t)Tn * KDIM / 16;
    gate_aconv_kernel<<<(unsigned)((atot + 255) / 256), 256>>>(x);

    dim3 grid(NEXP / BN, Tn / BM);   // (4, 128), bn fastest -> A L2 reuse
    gate_mma_gemm<<<grid, THREADS, SMEM_BYTES>>>();

    float* out_w = (float*)d_out;
    float* out_i = (float*)d_out + (size_t)Tn * 8;
    const int warps_per_block = 8;
    const int blocks = (Tn + warps_per_block - 1) / warps_per_block;
    gate_route_kernel<<<blocks, warps_per_block * 32>>>(bias, out_w, out_i, Tn);
}